// round 9
// baseline (speedup 1.0000x reference)
#include <cuda_runtime.h>
#include <math.h>

#define D 256
#define HALF_D 128
#define MAXN 4096
#define TM 128
#define TN 128
#define TK 32
#define SA_STRIDE 66   // f32x2 per k-row (pad: keeps 16B row alignment, spreads banks)
#define EMAX 2048
#define CAP 64         // CSR slots per row
#define HCAP 20        // CSR entries per (row, half) thread

// ---- device scratch (module-load zero-initialized; no allocations) ----
__device__ float g_G [D*D];          // G = R = I + 2(M + M^2 + ... + M^8)
__device__ float2 g_cs[MAXN*HALF_D]; // (cos,sin) per (position, freq-pair)
__device__ float2 g_csr[D*CAP];      // per-row edge list: (.x = col bits, .y = +/-val); unused slots stay 0
__device__ int    g_degh[D];         // entries in half 0 (quarters 0+1) per row

// packed-f32x2 helpers (Blackwell f32x2 pipe, PTX-only)
#define FMA2(d, a, b) asm("fma.rn.f32x2 %0, %1, %2, %0;" : "+l"(d) : "l"(a), "l"(b))
#define DUP2(d, f)    asm("mov.b64 %0, {%1, %1};" : "=l"(d) : "r"(__float_as_uint(f)))

// ---------------- CSR build: deterministic ordered scan, no atomics ----------------
// 1 block x 1024 threads. Thread (row = t&255, quarter h = t>>8) scans its quarter of the
// edge list in order, first counting then storing -> identical layout every replay.
__global__ void __launch_bounds__(1024) k_build(const int* __restrict__ rows,
                                                const int* __restrict__ cols,
                                                const float* __restrict__ sp, int E) {
    __shared__ int   sh_rc[EMAX];
    __shared__ float sh_v [EMAX];
    __shared__ unsigned short sh_cnt[4][D];
    int t = threadIdx.x;
    for (int e = t; e < E; e += 1024) {
        sh_rc[e] = (rows[e] << 16) | cols[e];
        sh_v [e] = sp[e];
    }
    __syncthreads();

    int row = t & 255, h = t >> 8;
    int e0 = (h * E) >> 2, e1 = ((h + 1) * E) >> 2;

    int cnt = 0;
    for (int e = e0; e < e1; e++) {
        int rc = sh_rc[e];
        int r = rc >> 16, c = rc & 0xFFFF;
        cnt += (r == row) + (c == row);
    }
    sh_cnt[h][row] = (unsigned short)cnt;
    __syncthreads();

    int base = row * CAP;
    for (int g = 0; g < h; g++) base += sh_cnt[g][row];

    int off = 0;
    for (int e = e0; e < e1; e++) {
        int rc = sh_rc[e];
        int r = rc >> 16, c = rc & 0xFFFF;
        float v = sh_v[e];
        if (r == row) g_csr[base + off++] = make_float2(__int_as_float(c),  v);
        else if (c == row) g_csr[base + off++] = make_float2(__int_as_float(r), -v);
    }
    if (h == 0) g_degh[row] = (int)sh_cnt[0][row] + (int)sh_cnt[1][row];
}

// ---------------- fused prep: G columns (CSR-gather Horner) + cos/sin table ----------------
// Blocks [0, D): block j computes G[:, j] via 8 sparse mat-vec Horner steps, gather-style.
// 512 threads: row = t&255, half = t>>8; each keeps <=HCAP (col, val) pairs in registers.
// Blocks [D, ...): cos/sin table entries.
__global__ void __launch_bounds__(512) k_prep(
        const int* __restrict__ pos, const float* __restrict__ freqs, int N) {
    int bx = blockIdx.x;
    int t  = threadIdx.x;

    if (bx >= D) {
        int idx = (bx - D) * 512 + t;
        int tableN = N * HALF_D;
        if (idx < tableN) {
            int n = idx >> 7, j = idx & (HALF_D - 1);
            float ang = (float)pos[n] * freqs[j];       // fp32 rounding matches ref
            const float INV2PI = 0.15915494309189535f;
            const float C1 = 6.2831854820251465f;       // float(2*pi)
            const float C2 = -1.7484556000744263e-7f;   // 2*pi - (double)C1
            float qf = rintf(ang * INV2PI);
            float r  = fmaf(-qf, C1, ang);
            r = fmaf(-qf, C2, r);
            g_cs[idx] = make_float2(__cosf(r), __sinf(r));
        }
        return;
    }

    __shared__ float u[D];
    __shared__ float yp[512];

    const int row = t & 255, h = t >> 8;
    const int j = bx;
    const int d0 = g_degh[row];
    const int base = row * CAP + (h ? d0 : 0);

    // Load my entries. Memory-safe: base+i < row*CAP + d0 + HCAP <= row*CAP + CAP.
    // Half 0 masks entries >= d0 (those slots hold half 1's data); half 1's tail
    // slots beyond the row's degree were never written and are zero -> FMA adds 0.
    float vv[HCAP]; int cc[HCAP];
    #pragma unroll
    for (int i = 0; i < HCAP; i++) {
        float2 e = g_csr[base + i];
        float v = e.y;
        if (h == 0 && i >= d0) v = 0.f;
        vv[i] = v;
        cc[i] = __float_as_int(e.x) & 255;   // safe index even for zero slots
    }

    float s = 0.f;
    #pragma unroll 1
    for (int it = 0; it < 8; it++) {
        if (h == 0) u[row] = s + (row == j ? 1.f : 0.f);
        __syncthreads();
        float part = 0.f;
        #pragma unroll
        for (int i = 0; i < HCAP; i++) part = fmaf(vv[i], u[cc[i]], part);
        yp[t] = part;
        __syncthreads();
        if (h == 0) s = yp[row] + yp[row + 256];
    }
    if (h == 0) g_G[row*D + j] = 2.f * s + (row == j ? 1.f : 0.f);
}

// ---------------- main GEMM: out = H_rope * G  (G includes identity) ----------------
// 128x128 block tile, 256 threads, 8x8 register tile per thread. Inner kc loop is
// software-pipelined: kc+1's A/B shared tiles prefetched into registers during kc's FMAs.
__global__ void __launch_bounds__(256, 2) k_gemm(const float* __restrict__ q,
                                                 const float* __restrict__ kk,
                                                 float* __restrict__ out,
                                                 int BN, int N) {
    __shared__ __align__(16) float2 sA[TK][SA_STRIDE];  // [kc][rowpair]
    __shared__ __align__(16) float  sB[TK][TN];         // [kc][col]

    const int t  = threadIdx.x;
    const int tx = t & 15;
    const int ty = t >> 4;
    const int row0 = blockIdx.x * TM;
    const int col0 = blockIdx.y * TN;

    const int jp = tx;     // staging: pair-within-chunk 0..15
    const int pb = ty;     // staging: rowpair base 0..15

    const float* src; int rb;
    if (row0 < BN) { src = q; rb = row0; } else { src = kk; rb = row0 - BN; }
    const int nb = rb % N;

    // prefetch A chunk 0
    float2 v[4][2];
    {
        const float* base = src + (size_t)rb*D + 2*jp;
        #pragma unroll
        for (int i = 0; i < 4; i++) {
            const float* rp = base + (size_t)(2*(pb + 16*i))*D;
            v[i][0] = *(const float2*)rp;
            v[i][1] = *(const float2*)(rp + D);
        }
    }

    unsigned long long acc[4][8];
    #pragma unroll
    for (int pp = 0; pp < 4; pp++)
        #pragma unroll
        for (int cc = 0; cc < 8; cc++) acc[pp][cc] = 0ull;

    for (int c = 0; c < D/TK; c++) {
        const int jpg = c*16 + jp;

        // ---- stage A with RoPE (from prefetched regs) ----
        #pragma unroll
        for (int i = 0; i < 4; i++) {
            int p  = pb + 16*i;
            int n0 = nb + 2*p;
            float2 cs0 = g_cs[n0*HALF_D + jpg];
            float2 cs1 = g_cs[(n0+1)*HALF_D + jpg];
            float2 a = v[i][0], b2 = v[i][1];
            float e0 = a.x*cs0.x  - a.y*cs0.y;
            float o0 = a.x*cs0.y  + a.y*cs0.x;
            float e1 = b2.x*cs1.x - b2.y*cs1.y;
            float o1 = b2.x*cs1.y + b2.y*cs1.x;
            sA[2*jp  ][p] = make_float2(e0, e1);
            sA[2*jp+1][p] = make_float2(o0, o1);
        }
        // ---- stage B (G slice, L2-hot) ----
        #pragma unroll
        for (int i = 0; i < 4; i++) {
            int lin = i*256 + t;
            int kc = lin >> 5, c4 = lin & 31;
            float4 bb = *(const float4*)&g_G[(size_t)(c*TK + kc)*D + col0 + c4*4];
            *(float4*)&sB[kc][c4*4] = bb;
        }
        __syncthreads();

        // ---- prefetch next A chunk from global (flies during compute) ----
        if (c < D/TK - 1) {
            const float* base = src + (size_t)rb*D + 2*((c+1)*16 + jp);
            #pragma unroll
            for (int i = 0; i < 4; i++) {
                const float* rp = base + (size_t)(2*(pb + 16*i))*D;
                v[i][0] = *(const float2*)rp;
                v[i][1] = *(const float2*)(rp + D);
            }
        }

        // ---- pipelined compute: preload kc=0, prefetch kc+1 during FMAs ----
        ulonglong2 A0c = *(const ulonglong2*)&sA[0][ty*4];
        ulonglong2 A1c = *(const ulonglong2*)&sA[0][ty*4 + 2];
        float4 b0c = *(const float4*)&sB[0][tx*4];
        float4 b1c = *(const float4*)&sB[0][tx*4 + 64];

        #pragma unroll 8
        for (int kc = 0; kc < TK; kc++) {
            int kn = (kc + 1) & (TK - 1);   // last iter harmlessly reloads kc=0
            ulonglong2 A0n = *(const ulonglong2*)&sA[kn][ty*4];
            ulonglong2 A1n = *(const ulonglong2*)&sA[kn][ty*4 + 2];
            float4 b0n = *(const float4*)&sB[kn][tx*4];
            float4 b1n = *(const float4*)&sB[kn][tx*4 + 64];

            unsigned long long g0,g1,g2,g3,g4,g5,g6,g7;
            DUP2(g0, b0c.x); DUP2(g1, b0c.y); DUP2(g2, b0c.z); DUP2(g3, b0c.w);
            DUP2(g4, b1c.x); DUP2(g5, b1c.y); DUP2(g6, b1c.z); DUP2(g7, b1c.w);
            unsigned long long Ap[4] = {A0c.x, A0c.y, A1c.x, A1c.y};
            #pragma unroll
            for (int pp = 0; pp < 4; pp++) {
                FMA2(acc[pp][0], Ap[pp], g0);
                FMA2(acc[pp][1], Ap[pp], g1);
                FMA2(acc[pp][2], Ap[pp], g2);
                FMA2(acc[pp][3], Ap[pp], g3);
                FMA2(acc[pp][4], Ap[pp], g4);
                FMA2(acc[pp][5], Ap[pp], g5);
                FMA2(acc[pp][6], Ap[pp], g6);
                FMA2(acc[pp][7], Ap[pp], g7);
            }
            A0c = A0n; A1c = A1n; b0c = b0n; b1c = b1n;
        }
        __syncthreads();
    }

    // ---- epilogue: unpack row-pair f32x2 accumulators, STG.128 per row segment ----
    #pragma unroll
    for (int pp = 0; pp < 4; pp++) {
        int re = row0 + (ty*4 + pp)*2;
        float4 lo0, hi0, lo1, hi1;
        lo0.x = __uint_as_float((unsigned)acc[pp][0]); hi0.x = __uint_as_float((unsigned)(acc[pp][0] >> 32));
        lo0.y = __uint_as_float((unsigned)acc[pp][1]); hi0.y = __uint_as_float((unsigned)(acc[pp][1] >> 32));
        lo0.z = __uint_as_float((unsigned)acc[pp][2]); hi0.z = __uint_as_float((unsigned)(acc[pp][2] >> 32));
        lo0.w = __uint_as_float((unsigned)acc[pp][3]); hi0.w = __uint_as_float((unsigned)(acc[pp][3] >> 32));
        lo1.x = __uint_as_float((unsigned)acc[pp][4]); hi1.x = __uint_as_float((unsigned)(acc[pp][4] >> 32));
        lo1.y = __uint_as_float((unsigned)acc[pp][5]); hi1.y = __uint_as_float((unsigned)(acc[pp][5] >> 32));
        lo1.z = __uint_as_float((unsigned)acc[pp][6]); hi1.z = __uint_as_float((unsigned)(acc[pp][6] >> 32));
        lo1.w = __uint_as_float((unsigned)acc[pp][7]); hi1.w = __uint_as_float((unsigned)(acc[pp][7] >> 32));
        *(float4*)&out[(size_t)re*D     + col0 + tx*4]      = lo0;
        *(float4*)&out[(size_t)(re+1)*D + col0 + tx*4]      = hi0;
        *(float4*)&out[(size_t)re*D     + col0 + 64 + tx*4] = lo1;
        *(float4*)&out[(size_t)(re+1)*D + col0 + 64 + tx*4] = hi1;
    }
}

// ---------------- launcher: 3 launches total ----------------
extern "C" void kernel_launch(void* const* d_in, const int* in_sizes, int n_in,
                              void* d_out, int out_size) {
    const float* q     = (const float*)d_in[0];
    const float* k     = (const float*)d_in[1];
    const float* freqs = (const float*)d_in[2];
    const float* sp    = (const float*)d_in[3];
    const int*   pos   = (const int*)  d_in[4];
    const int*   rows  = (const int*)  d_in[5];
    const int*   cols  = (const int*)  d_in[6];
    float* out = (float*)d_out;

    int E    = in_sizes[3];
    int N    = in_sizes[4];
    int BN   = in_sizes[0] / D;   // rows of q (= B*N)
    int ROWS = 2 * BN;

    k_build<<<1, 1024>>>(rows, cols, sp, E);

    int tableBlocks = (N*HALF_D + 511)/512;
    k_prep<<<D + tableBlocks, 512>>>(pos, freqs, N);

    dim3 grid(ROWS/TM, D/TN);
    k_gemm<<<grid, 256>>>(q, k, out, BN, N);
}

// round 10
// speedup vs baseline: 1.5507x; 1.5507x over previous
#include <cuda_runtime.h>
#include <math.h>

#define D 256
#define HALF_D 128
#define MAXN 4096
#define TM 128
#define TN 128
#define TK 32
#define SA_STRIDE 66   // f32x2 per k-row (pad: keeps 16B row alignment, spreads banks)
#define CAP 64         // CSR slots per row
#define HCAP 20        // CSR entries per (row, half) thread

// ---- device scratch (module-load zero-initialized; no allocations) ----
__device__ float g_G [D*D];          // G = R = I + 2(M + M^2 + ... + M^8)
__device__ float2 g_cs[MAXN*HALF_D]; // (cos,sin) per (position, freq-pair)
__device__ float2 g_csr[D*CAP];      // per-row edge list: (.x = col bits, .y = +/-val); unused slots stay 0
__device__ int    g_degh[D];         // = deg(row)/2 : entries assigned to half 0

// packed-f32x2 helpers (Blackwell f32x2 pipe, PTX-only)
#define FMA2(d, a, b) asm("fma.rn.f32x2 %0, %1, %2, %0;" : "+l"(d) : "l"(a), "l"(b))
#define DUP2(d, f)    asm("mov.b64 %0, {%1, %1};" : "=l"(d) : "r"(__float_as_uint(f)))

// ---------------- CSR build: warp-per-row, ballot-ordered, no atomics ----------------
// 32 blocks x 256 threads = 256 warps; warp w owns row w. Deterministic: placement
// order equals edge order via ballot+popc prefix, identical every replay.
__global__ void __launch_bounds__(256) k_build(const int* __restrict__ rows,
                                               const int* __restrict__ cols,
                                               const float* __restrict__ sp, int E) {
    int row  = (blockIdx.x << 3) + (threadIdx.x >> 5);
    int lane = threadIdx.x & 31;

    int off = 0;
    for (int e0 = 0; e0 < E; e0 += 32) {
        int e = e0 + lane;
        bool valid = e < E;
        int r = valid ? rows[e] : -1;
        int c = valid ? cols[e] : -1;
        bool isr = (r == row);
        bool hit = isr | (c == row);
        unsigned mask = __ballot_sync(0xFFFFFFFFu, hit);
        if (hit) {
            float v = sp[e];
            int pos = off + __popc(mask & ((1u << lane) - 1u));
            g_csr[row*CAP + pos] =
                make_float2(__int_as_float(isr ? c : r), isr ? v : -v);
        }
        off += __popc(mask);
    }
    if (lane == 0) g_degh[row] = off >> 1;
}

// ---------------- fused prep: G columns (CSR-gather Horner) + cos/sin table ----------------
// Blocks [0, D): block j computes G[:, j] via 8 sparse mat-vec Horner steps, gather-style.
// 512 threads: row = t&255, half = t>>8; each keeps <=HCAP (col, val) pairs in registers.
// Blocks [D, ...): cos/sin table entries.
__global__ void __launch_bounds__(512) k_prep(
        const int* __restrict__ pos, const float* __restrict__ freqs, int N) {
    int bx = blockIdx.x;
    int t  = threadIdx.x;

    if (bx >= D) {
        int idx = (bx - D) * 512 + t;
        int tableN = N * HALF_D;
        if (idx < tableN) {
            int n = idx >> 7, j = idx & (HALF_D - 1);
            float ang = (float)pos[n] * freqs[j];       // fp32 rounding matches ref
            const float INV2PI = 0.15915494309189535f;
            const float C1 = 6.2831854820251465f;       // float(2*pi)
            const float C2 = -1.7484556000744263e-7f;   // 2*pi - (double)C1
            float qf = rintf(ang * INV2PI);
            float r  = fmaf(-qf, C1, ang);
            r = fmaf(-qf, C2, r);
            g_cs[idx] = make_float2(__cosf(r), __sinf(r));
        }
        return;
    }

    __shared__ float u[D];
    __shared__ float yp[512];

    const int row = t & 255, h = t >> 8;
    const int j = bx;
    const int d0 = g_degh[row];
    const int base = row * CAP + (h ? d0 : 0);

    // Half 0 owns entries [0, d0); half 1 owns [d0, deg). Slots beyond deg were
    // never written and stay zero -> their FMA contribution is 0. Half 0 must
    // mask i >= d0 (those slots hold half 1's live data).
    float vv[HCAP]; int cc[HCAP];
    #pragma unroll
    for (int i = 0; i < HCAP; i++) {
        float2 e = g_csr[base + i];
        float v = e.y;
        if (h == 0 && i >= d0) v = 0.f;
        vv[i] = v;
        cc[i] = __float_as_int(e.x) & 255;   // safe index even for zero slots
    }

    float s = 0.f;
    #pragma unroll 1
    for (int it = 0; it < 8; it++) {
        if (h == 0) u[row] = s + (row == j ? 1.f : 0.f);
        __syncthreads();
        float part = 0.f;
        #pragma unroll
        for (int i = 0; i < HCAP; i++) part = fmaf(vv[i], u[cc[i]], part);
        yp[t] = part;
        __syncthreads();
        if (h == 0) s = yp[row] + yp[row + 256];
    }
    if (h == 0) g_G[row*D + j] = 2.f * s + (row == j ? 1.f : 0.f);
}

// ---------------- main GEMM: out = H_rope * G  (G includes identity) ----------------
// 128x128 block tile, 256 threads, 8x8 register tile per thread. Inner kc loop is
// software-pipelined: kc+1's A/B shared tiles prefetched into registers during kc's FMAs.
__global__ void __launch_bounds__(256, 2) k_gemm(const float* __restrict__ q,
                                                 const float* __restrict__ kk,
                                                 float* __restrict__ out,
                                                 int BN, int N) {
    __shared__ __align__(16) float2 sA[TK][SA_STRIDE];  // [kc][rowpair]
    __shared__ __align__(16) float  sB[TK][TN];         // [kc][col]

    const int t  = threadIdx.x;
    const int tx = t & 15;
    const int ty = t >> 4;
    const int row0 = blockIdx.x * TM;
    const int col0 = blockIdx.y * TN;

    const int jp = tx;     // staging: pair-within-chunk 0..15
    const int pb = ty;     // staging: rowpair base 0..15

    const float* src; int rb;
    if (row0 < BN) { src = q; rb = row0; } else { src = kk; rb = row0 - BN; }
    const int nb = rb % N;

    // prefetch A chunk 0
    float2 v[4][2];
    {
        const float* base = src + (size_t)rb*D + 2*jp;
        #pragma unroll
        for (int i = 0; i < 4; i++) {
            const float* rp = base + (size_t)(2*(pb + 16*i))*D;
            v[i][0] = *(const float2*)rp;
            v[i][1] = *(const float2*)(rp + D);
        }
    }

    unsigned long long acc[4][8];
    #pragma unroll
    for (int pp = 0; pp < 4; pp++)
        #pragma unroll
        for (int cc = 0; cc < 8; cc++) acc[pp][cc] = 0ull;

    for (int c = 0; c < D/TK; c++) {
        const int jpg = c*16 + jp;

        // ---- stage A with RoPE (from prefetched regs) ----
        #pragma unroll
        for (int i = 0; i < 4; i++) {
            int p  = pb + 16*i;
            int n0 = nb + 2*p;
            float2 cs0 = g_cs[n0*HALF_D + jpg];
            float2 cs1 = g_cs[(n0+1)*HALF_D + jpg];
            float2 a = v[i][0], b2 = v[i][1];
            float e0 = a.x*cs0.x  - a.y*cs0.y;
            float o0 = a.x*cs0.y  + a.y*cs0.x;
            float e1 = b2.x*cs1.x - b2.y*cs1.y;
            float o1 = b2.x*cs1.y + b2.y*cs1.x;
            sA[2*jp  ][p] = make_float2(e0, e1);
            sA[2*jp+1][p] = make_float2(o0, o1);
        }
        // ---- stage B (G slice, L2-hot) ----
        #pragma unroll
        for (int i = 0; i < 4; i++) {
            int lin = i*256 + t;
            int kc = lin >> 5, c4 = lin & 31;
            float4 bb = *(const float4*)&g_G[(size_t)(c*TK + kc)*D + col0 + c4*4];
            *(float4*)&sB[kc][c4*4] = bb;
        }
        __syncthreads();

        // ---- prefetch next A chunk from global (flies during compute) ----
        if (c < D/TK - 1) {
            const float* base = src + (size_t)rb*D + 2*((c+1)*16 + jp);
            #pragma unroll
            for (int i = 0; i < 4; i++) {
                const float* rp = base + (size_t)(2*(pb + 16*i))*D;
                v[i][0] = *(const float2*)rp;
                v[i][1] = *(const float2*)(rp + D);
            }
        }

        // ---- pipelined compute: preload kc=0, prefetch kc+1 during FMAs ----
        ulonglong2 A0c = *(const ulonglong2*)&sA[0][ty*4];
        ulonglong2 A1c = *(const ulonglong2*)&sA[0][ty*4 + 2];
        float4 b0c = *(const float4*)&sB[0][tx*4];
        float4 b1c = *(const float4*)&sB[0][tx*4 + 64];

        #pragma unroll 8
        for (int kc = 0; kc < TK; kc++) {
            int kn = (kc + 1) & (TK - 1);   // last iter harmlessly reloads kc=0
            ulonglong2 A0n = *(const ulonglong2*)&sA[kn][ty*4];
            ulonglong2 A1n = *(const ulonglong2*)&sA[kn][ty*4 + 2];
            float4 b0n = *(const float4*)&sB[kn][tx*4];
            float4 b1n = *(const float4*)&sB[kn][tx*4 + 64];

            unsigned long long g0,g1,g2,g3,g4,g5,g6,g7;
            DUP2(g0, b0c.x); DUP2(g1, b0c.y); DUP2(g2, b0c.z); DUP2(g3, b0c.w);
            DUP2(g4, b1c.x); DUP2(g5, b1c.y); DUP2(g6, b1c.z); DUP2(g7, b1c.w);
            unsigned long long Ap[4] = {A0c.x, A0c.y, A1c.x, A1c.y};
            #pragma unroll
            for (int pp = 0; pp < 4; pp++) {
                FMA2(acc[pp][0], Ap[pp], g0);
                FMA2(acc[pp][1], Ap[pp], g1);
                FMA2(acc[pp][2], Ap[pp], g2);
                FMA2(acc[pp][3], Ap[pp], g3);
                FMA2(acc[pp][4], Ap[pp], g4);
                FMA2(acc[pp][5], Ap[pp], g5);
                FMA2(acc[pp][6], Ap[pp], g6);
                FMA2(acc[pp][7], Ap[pp], g7);
            }
            A0c = A0n; A1c = A1n; b0c = b0n; b1c = b1n;
        }
        __syncthreads();
    }

    // ---- epilogue: unpack row-pair f32x2 accumulators, STG.128 per row segment ----
    #pragma unroll
    for (int pp = 0; pp < 4; pp++) {
        int re = row0 + (ty*4 + pp)*2;
        float4 lo0, hi0, lo1, hi1;
        lo0.x = __uint_as_float((unsigned)acc[pp][0]); hi0.x = __uint_as_float((unsigned)(acc[pp][0] >> 32));
        lo0.y = __uint_as_float((unsigned)acc[pp][1]); hi0.y = __uint_as_float((unsigned)(acc[pp][1] >> 32));
        lo0.z = __uint_as_float((unsigned)acc[pp][2]); hi0.z = __uint_as_float((unsigned)(acc[pp][2] >> 32));
        lo0.w = __uint_as_float((unsigned)acc[pp][3]); hi0.w = __uint_as_float((unsigned)(acc[pp][3] >> 32));
        lo1.x = __uint_as_float((unsigned)acc[pp][4]); hi1.x = __uint_as_float((unsigned)(acc[pp][4] >> 32));
        lo1.y = __uint_as_float((unsigned)acc[pp][5]); hi1.y = __uint_as_float((unsigned)(acc[pp][5] >> 32));
        lo1.z = __uint_as_float((unsigned)acc[pp][6]); hi1.z = __uint_as_float((unsigned)(acc[pp][6] >> 32));
        lo1.w = __uint_as_float((unsigned)acc[pp][7]); hi1.w = __uint_as_float((unsigned)(acc[pp][7] >> 32));
        *(float4*)&out[(size_t)re*D     + col0 + tx*4]      = lo0;
        *(float4*)&out[(size_t)(re+1)*D + col0 + tx*4]      = hi0;
        *(float4*)&out[(size_t)re*D     + col0 + 64 + tx*4] = lo1;
        *(float4*)&out[(size_t)(re+1)*D + col0 + 64 + tx*4] = hi1;
    }
}

// ---------------- launcher: 3 launches total ----------------
extern "C" void kernel_launch(void* const* d_in, const int* in_sizes, int n_in,
                              void* d_out, int out_size) {
    const float* q     = (const float*)d_in[0];
    const float* k     = (const float*)d_in[1];
    const float* freqs = (const float*)d_in[2];
    const float* sp    = (const float*)d_in[3];
    const int*   pos   = (const int*)  d_in[4];
    const int*   rows  = (const int*)  d_in[5];
    const int*   cols  = (const int*)  d_in[6];
    float* out = (float*)d_out;

    int E    = in_sizes[3];
    int N    = in_sizes[4];
    int BN   = in_sizes[0] / D;   // rows of q (= B*N)
    int ROWS = 2 * BN;

    k_build<<<32, 256>>>(rows, cols, sp, E);

    int tableBlocks = (N*HALF_D + 511)/512;
    k_prep<<<D + tableBlocks, 512>>>(pos, freqs, N);

    dim3 grid(ROWS/TM, D/TN);
    k_gemm<<<grid, 256>>>(q, k, out, BN, N);
}

// round 12
// speedup vs baseline: 1.8419x; 1.1878x over previous
#include <cuda_runtime.h>
#include <cuda_bf16.h>
#include <math.h>
#include <stdint.h>

#define D 256
#define HALF_D 128
#define MAXN 4096
#define CAP 64         // CSR slots per row
#define HCAP 20        // CSR entries per (row, half) thread
#define TILE_M 128
#define TILE_N 128

// dynamic smem for k_mma: fragment-order tiles, one K-chunk (64) at a time
//   sAhi/sAlo: [f:8][s:4][lane:32][reg:4] uint32 = 16KB each
//   sBhi/sBlo: [nf:16][s:4][lane:32][reg:2] uint32 = 16KB each
#define SMEM_U32 16384
#define SMEM_BYTES 65536

// ---- device scratch (module-load zero-initialized; no allocations) ----
__device__ __align__(16) float2 g_cs[MAXN*HALF_D]; // (cos,sin) per (position, freq-pair)
__device__ float2 g_csr[D*CAP];                    // per-row edges (.x=col bits, .y=+/-val)
__device__ int    g_degh[D];                       // deg/2 per row
__device__ __align__(16) __nv_bfloat16 g_Cthi[D*D]; // B^T hi:  [n][k] = bf16(G[k][n])
__device__ __align__(16) __nv_bfloat16 g_Ctlo[D*D]; // B^T lo residual

// bf16 HMMA, baseline PTX (sm_80+), fp32 accumulate in registers
__device__ __forceinline__ void mma16816(float* c, const uint4 a, const uint2 b) {
    asm volatile(
        "mma.sync.aligned.m16n8k16.row.col.f32.bf16.bf16.f32 "
        "{%0,%1,%2,%3}, {%4,%5,%6,%7}, {%8,%9}, {%0,%1,%2,%3};"
        : "+f"(c[0]), "+f"(c[1]), "+f"(c[2]), "+f"(c[3])
        : "r"(a.x), "r"(a.y), "r"(a.z), "r"(a.w), "r"(b.x), "r"(b.y));
}

// ---------------- CSR build: warp-per-row, batched loads + ballot-ordered ----------------
__global__ void __launch_bounds__(256) k_build(const int* __restrict__ rows,
                                               const int* __restrict__ cols,
                                               const float* __restrict__ sp, int E) {
    int row  = (blockIdx.x << 3) + (threadIdx.x >> 5);
    int lane = threadIdx.x & 31;

    int off = 0;
    for (int e0 = 0; e0 < E; e0 += 256) {
        int rr[8], cc[8];
        #pragma unroll
        for (int b = 0; b < 8; b++) {           // 16 independent LDGs -> MLP hides latency
            int e = e0 + b*32 + lane;
            bool v = e < E;
            rr[b] = v ? rows[e] : -1;
            cc[b] = v ? cols[e] : -1;
        }
        #pragma unroll
        for (int b = 0; b < 8; b++) {
            bool isr = (rr[b] == row);
            bool hit = isr | (cc[b] == row);
            unsigned mask = __ballot_sync(0xFFFFFFFFu, hit);
            if (hit) {
                int e = e0 + b*32 + lane;
                float v = sp[e];
                int pos = off + __popc(mask & ((1u << lane) - 1u));
                g_csr[row*CAP + pos] =
                    make_float2(__int_as_float(isr ? cc[b] : rr[b]), isr ? v : -v);
            }
            off += __popc(mask);
        }
    }
    if (lane == 0) g_degh[row] = off >> 1;
}

// ---------------- fused prep: B^T hi/lo columns (CSR Horner) + cos/sin table ----------------
__global__ void __launch_bounds__(512) k_prep(
        const int* __restrict__ pos, const float* __restrict__ freqs, int N) {
    int bx = blockIdx.x;
    int t  = threadIdx.x;

    if (bx >= D) {
        int idx = (bx - D) * 512 + t;
        int tableN = N * HALF_D;
        if (idx < tableN) {
            int n = idx >> 7, j = idx & (HALF_D - 1);
            float ang = (float)pos[n] * freqs[j];       // fp32 rounding matches ref
            const float INV2PI = 0.15915494309189535f;
            const float C1 = 6.2831854820251465f;
            const float C2 = -1.7484556000744263e-7f;
            float qf = rintf(ang * INV2PI);
            float r  = fmaf(-qf, C1, ang);
            r = fmaf(-qf, C2, r);
            g_cs[idx] = make_float2(__cosf(r), __sinf(r));
        }
        return;
    }

    __shared__ float u[D];
    __shared__ float yp[512];

    const int row = t & 255, h = t >> 8;
    const int j = bx;
    const int d0 = g_degh[row];
    const int base = row * CAP + (h ? d0 : 0);

    float vv[HCAP]; int cc[HCAP];
    #pragma unroll
    for (int i = 0; i < HCAP; i++) {
        float2 e = g_csr[base + i];
        float v = e.y;
        if (h == 0 && i >= d0) v = 0.f;      // those slots hold half-1 data
        vv[i] = v;                            // half-1 tail slots are zero -> adds 0
        cc[i] = __float_as_int(e.x) & 255;
    }

    float s = 0.f;
    #pragma unroll 1
    for (int it = 0; it < 8; it++) {
        if (h == 0) u[row] = s + (row == j ? 1.f : 0.f);
        __syncthreads();
        float part = 0.f;
        #pragma unroll
        for (int i = 0; i < HCAP; i++) part = fmaf(vv[i], u[cc[i]], part);
        yp[t] = part;
        __syncthreads();
        if (h == 0) s = yp[row] + yp[row + 256];
    }
    if (h == 0) {
        float val = 2.f * s + (row == j ? 1.f : 0.f);   // G = I + 2*Sum M^i
        __nv_bfloat16 hi = __float2bfloat16(val);
        float lo = val - __bfloat162float(hi);
        g_Cthi[j*D + row] = hi;                         // [n=j][k=row], coalesced
        g_Ctlo[j*D + row] = __float2bfloat16(lo);
    }
}

// ---------------- main GEMM via HMMA: out = (Ahi+Alo)Bhi + Ahi*Blo ----------------
// 128x128 tile, 256 threads = 8 warps (4 x 2), warp tile 32(M) x 64(N), K chunks of 64.
// A/B staged in smem directly in m16n8k16 fragment order:
//   A element (m, k):  f=m>>4, s=k>>4, lane=(m&7)*4+((k&7)>>1), reg=((m>>3)&1)+2*((k>>3)&1)
//   B element (k, n): nf=n>>3, s=k>>4, lane=(n&7)*4+((k&7)>>1), reg=(k>>3)&1
__global__ void __launch_bounds__(256) k_mma(const float* __restrict__ q,
                                             const float* __restrict__ kk,
                                             float* __restrict__ out,
                                             int BN, int N) {
    extern __shared__ uint32_t sm[];
    uint32_t* sAhi = sm;
    uint32_t* sAlo = sm + 4096;
    uint32_t* sBhi = sm + 8192;
    uint32_t* sBlo = sm + 12288;

    const int t = threadIdx.x, lane = t & 31, wid = t >> 5;
    const int wr = wid >> 1, wc = wid & 1;
    const int row0 = blockIdx.x * TILE_M;
    const int col0 = blockIdx.y * TILE_N;

    const float* src; int rb;
    if (row0 < BN) { src = q; rb = row0; } else { src = kk; rb = row0 - BN; }
    const int nb = rb % N;   // tile never crosses batch boundary (N multiple of 128)

    float acc[2][8][4];
    #pragma unroll
    for (int f2 = 0; f2 < 2; f2++)
        #pragma unroll
        for (int b2 = 0; b2 < 8; b2++)
            #pragma unroll
            for (int e = 0; e < 4; e++) acc[f2][b2][e] = 0.f;

    const uint32_t* Bhi32 = (const uint32_t*)g_Cthi;
    const uint32_t* Blo32 = (const uint32_t*)g_Ctlo;

    for (int ch = 0; ch < 4; ch++) {
        // ---- stage A chunk with RoPE + hi/lo split (16 u32 per thread) ----
        #pragma unroll 4
        for (int i = 0; i < 16; i++) {
            int idx = i*256 + t;
            int m = idx >> 5, pj = idx & 31;     // local k-pair pj -> k = 2*pj
            int jp = ch*32 + pj;                 // global rotation pair
            float2 v  = *(const float2*)(src + (size_t)(rb + m)*D + 2*jp);
            float2 cs = g_cs[(size_t)(nb + m)*HALF_D + jp];
            float e = v.x*cs.x - v.y*cs.y;
            float o = v.x*cs.y + v.y*cs.x;
            __nv_bfloat16 he = __float2bfloat16(e), ho = __float2bfloat16(o);
            uint32_t hp = ((uint32_t)__bfloat16_as_ushort(ho) << 16) | __bfloat16_as_ushort(he);
            float le = e - __bfloat162float(he), lo = o - __bfloat162float(ho);
            __nv_bfloat16 ge = __float2bfloat16(le), go = __float2bfloat16(lo);
            uint32_t lp = ((uint32_t)__bfloat16_as_ushort(go) << 16) | __bfloat16_as_ushort(ge);
            int addr = ((((m>>4)*4 + (pj>>3))*32 + (m&7)*4 + (pj&3)) << 2)
                     + ((m>>3)&1) + 2*((pj>>2)&1);
            sAhi[addr] = hp;
            sAlo[addr] = lp;
        }
        // ---- stage B chunk from precomputed B^T (16 u32 per thread each) ----
        #pragma unroll 4
        for (int i = 0; i < 16; i++) {
            int idx = i*256 + t;
            int n = idx >> 5, pj = idx & 31;
            int gidx = (col0 + n)*(D/2) + ch*32 + pj;   // u32 index into [n][k] bf16
            uint32_t vh = Bhi32[gidx];
            uint32_t vl = Blo32[gidx];
            int addr = ((((n>>3)*4 + (pj>>3))*32 + (n&7)*4 + (pj&3)) << 1)
                     + ((pj>>2)&1);
            sBhi[addr] = vh;
            sBlo[addr] = vl;
        }
        __syncthreads();

        // ---- compute: 4 k16-steps, 3 passes ----
        #pragma unroll
        for (int s = 0; s < 4; s++) {
            uint4 ah0 = ((const uint4*)sAhi)[((wr*2 + 0)*4 + s)*32 + lane];
            uint4 ah1 = ((const uint4*)sAhi)[((wr*2 + 1)*4 + s)*32 + lane];
            uint4 al0 = ((const uint4*)sAlo)[((wr*2 + 0)*4 + s)*32 + lane];
            uint4 al1 = ((const uint4*)sAlo)[((wr*2 + 1)*4 + s)*32 + lane];
            #pragma unroll
            for (int b2 = 0; b2 < 8; b2++) {
                uint2 bh = ((const uint2*)sBhi)[((wc*8 + b2)*4 + s)*32 + lane];
                uint2 bl = ((const uint2*)sBlo)[((wc*8 + b2)*4 + s)*32 + lane];
                mma16816(acc[0][b2], ah0, bh);
                mma16816(acc[1][b2], ah1, bh);
                mma16816(acc[0][b2], al0, bh);
                mma16816(acc[1][b2], al1, bh);
                mma16816(acc[0][b2], ah0, bl);
                mma16816(acc[1][b2], ah1, bl);
            }
        }
        __syncthreads();
    }

    // ---- epilogue: fragment -> out (float2 stores) ----
    const int g  = lane >> 2, tq = lane & 3;
    #pragma unroll
    for (int f2 = 0; f2 < 2; f2++) {
        int m0 = row0 + (wr*2 + f2)*16 + g;
        #pragma unroll
        for (int b2 = 0; b2 < 8; b2++) {
            int n0 = col0 + (wc*8 + b2)*8 + tq*2;
            *(float2*)&out[(size_t)m0*D + n0]     = make_float2(acc[f2][b2][0], acc[f2][b2][1]);
            *(float2*)&out[(size_t)(m0+8)*D + n0] = make_float2(acc[f2][b2][2], acc[f2][b2][3]);
        }
    }
}

// ---------------- launcher: 3 launches total ----------------
extern "C" void kernel_launch(void* const* d_in, const int* in_sizes, int n_in,
                              void* d_out, int out_size) {
    const float* q     = (const float*)d_in[0];
    const float* k     = (const float*)d_in[1];
    const float* freqs = (const float*)d_in[2];
    const float* sp    = (const float*)d_in[3];
    const int*   pos   = (const int*)  d_in[4];
    const int*   rows  = (const int*)  d_in[5];
    const int*   cols  = (const int*)  d_in[6];
    float* out = (float*)d_out;

    int E    = in_sizes[3];
    int N    = in_sizes[4];
    int BN   = in_sizes[0] / D;   // rows of q (= B*N)
    int ROWS = 2 * BN;

    k_build<<<32, 256>>>(rows, cols, sp, E);

    int tableBlocks = (N*HALF_D + 511)/512;
    k_prep<<<D + tableBlocks, 512>>>(pos, freqs, N);

    static bool attrSet = false;
    if (!attrSet) {
        cudaFuncSetAttribute(k_mma, cudaFuncAttributeMaxDynamicSharedMemorySize, SMEM_BYTES);
        attrSet = true;
    }
    dim3 grid(ROWS/TILE_M, D/TILE_N);
    k_mma<<<grid, 256, SMEM_BYTES>>>(q, k, out, BN, N);
}

// round 14
// speedup vs baseline: 1.8480x; 1.0033x over previous
#include <cuda_runtime.h>
#include <cuda_bf16.h>
#include <math.h>
#include <stdint.h>

#define D 256
#define HALF_D 128
#define MAXN 4096
#define CAP 64         // CSR slots per row
#define HCAP 20        // CSR entries per (row, half) thread
#define TILE_M 128
#define TILE_N 128

// dynamic smem for k_mma: fragment-order tiles, one K-chunk (64) at a time
#define SMEM_BYTES 65536

// ---- device scratch (module-load zero-initialized; no allocations) ----
__device__ __align__(16) float2 g_cs[MAXN*HALF_D]; // (cos,sin) per (position, freq-pair)
__device__ float2 g_csr[D*CAP];                    // per-row edges (.x=col bits, .y=+/-val)
__device__ int    g_degh[D];                       // deg/2 per row
__device__ __align__(16) __nv_bfloat16 g_Cthi[D*D]; // B^T hi:  [n][k] = bf16(G[k][n])
__device__ __align__(16) __nv_bfloat16 g_Ctlo[D*D]; // B^T lo residual

// bf16 HMMA, baseline PTX (sm_80+), fp32 accumulate in registers
__device__ __forceinline__ void mma16816(float* c, const uint4 a, const uint2 b) {
    asm volatile(
        "mma.sync.aligned.m16n8k16.row.col.f32.bf16.bf16.f32 "
        "{%0,%1,%2,%3}, {%4,%5,%6,%7}, {%8,%9}, {%0,%1,%2,%3};"
        : "+f"(c[0]), "+f"(c[1]), "+f"(c[2]), "+f"(c[3])
        : "r"(a.x), "r"(a.y), "r"(a.z), "r"(a.w), "r"(b.x), "r"(b.y));
}

// ---------------- CSR build v3: block-per-row, coalesced chunk + block prefix scan ----------------
// 256 blocks (one per row) x 256 threads. Chunk of 256 edges loaded one-per-thread
// (coalesced); hit positions via warp ballot + 8-warp prefix. Order = edge order
// (deterministic, identical layout to the warp-scan builder).
__global__ void __launch_bounds__(256) k_build(const int* __restrict__ rows,
                                               const int* __restrict__ cols,
                                               const float* __restrict__ sp, int E) {
    __shared__ int warpsum[8];
    const int row  = blockIdx.x;
    const int t    = threadIdx.x;
    const int lane = t & 31, wid = t >> 5;

    int running = 0;
    for (int e0 = 0; e0 < E; e0 += 256) {
        int e = e0 + t;
        bool valid = e < E;
        int r = valid ? rows[e] : -1;
        int c = valid ? cols[e] : -1;
        bool isr = (r == row);
        bool hit = isr || (c == row);
        unsigned mask = __ballot_sync(0xFFFFFFFFu, hit);
        if (lane == 0) warpsum[wid] = __popc(mask);
        __syncthreads();
        int base = running, tot = 0;
        #pragma unroll
        for (int w = 0; w < 8; w++) {
            int ws = warpsum[w];
            if (w < wid) base += ws;
            tot += ws;
        }
        running += tot;
        if (hit) {
            float v = sp[e];
            int pos = base + __popc(mask & ((1u << lane) - 1u));
            g_csr[row*CAP + pos] =
                make_float2(__int_as_float(isr ? c : r), isr ? v : -v);
        }
        __syncthreads();   // warpsum reused next chunk
    }
    if (t == 0) g_degh[row] = running >> 1;
}

// ---------------- fused prep v2: 4 G-columns per block (float4 Horner) + cos/sin table ----------------
// Blocks [0, 64): block b computes G[:, 4b..4b+3] via 8 sparse Horner steps; the four
// column states live interleaved in float4 u4[] so one LDS.128 gather serves 4 columns.
// Blocks [64, ...): cos/sin table entries.
__global__ void __launch_bounds__(512) k_prep(
        const int* __restrict__ pos, const float* __restrict__ freqs, int N) {
    int bx = blockIdx.x;
    int t  = threadIdx.x;

    if (bx >= 64) {
        int idx = (bx - 64) * 512 + t;
        int tableN = N * HALF_D;
        if (idx < tableN) {
            int n = idx >> 7, j = idx & (HALF_D - 1);
            float ang = (float)pos[n] * freqs[j];       // fp32 rounding matches ref
            const float INV2PI = 0.15915494309189535f;
            const float C1 = 6.2831854820251465f;
            const float C2 = -1.7484556000744263e-7f;
            float qf = rintf(ang * INV2PI);
            float r  = fmaf(-qf, C1, ang);
            r = fmaf(-qf, C2, r);
            g_cs[idx] = make_float2(__cosf(r), __sinf(r));
        }
        return;
    }

    __shared__ __align__(16) float4 u4[D];
    __shared__ __align__(16) float4 yp4[512];

    const int row = t & 255, h = t >> 8;
    const int j0 = bx * 4;
    const int d0 = g_degh[row];
    const int base = row * CAP + (h ? d0 : 0);

    // Half 0 owns entries [0, d0); half 1 owns [d0, deg). Tail slots beyond deg are
    // zero (FMA adds 0); half 0 masks i >= d0 (those slots hold half-1 data).
    float vv[HCAP]; int cc[HCAP];
    #pragma unroll
    for (int i = 0; i < HCAP; i++) {
        float2 e = g_csr[base + i];
        float v = e.y;
        if (h == 0 && i >= d0) v = 0.f;
        vv[i] = v;
        cc[i] = __float_as_int(e.x) & 255;
    }

    float4 s = make_float4(0.f, 0.f, 0.f, 0.f);
    #pragma unroll 1
    for (int it = 0; it < 8; it++) {
        if (h == 0) {
            float4 uu = s;
            if (row == j0    ) uu.x += 1.f;
            if (row == j0 + 1) uu.y += 1.f;
            if (row == j0 + 2) uu.z += 1.f;
            if (row == j0 + 3) uu.w += 1.f;
            u4[row] = uu;
        }
        __syncthreads();
        float4 part = make_float4(0.f, 0.f, 0.f, 0.f);
        #pragma unroll
        for (int i = 0; i < HCAP; i++) {
            float4 uv = u4[cc[i]];
            part.x = fmaf(vv[i], uv.x, part.x);
            part.y = fmaf(vv[i], uv.y, part.y);
            part.z = fmaf(vv[i], uv.z, part.z);
            part.w = fmaf(vv[i], uv.w, part.w);
        }
        yp4[t] = part;
        __syncthreads();
        if (h == 0) {
            float4 a = yp4[row], b = yp4[row + 256];
            s = make_float4(a.x + b.x, a.y + b.y, a.z + b.z, a.w + b.w);
        }
    }
    if (h == 0) {
        float sv[4] = {s.x, s.y, s.z, s.w};
        #pragma unroll
        for (int c = 0; c < 4; c++) {
            float val = 2.f * sv[c] + (row == j0 + c ? 1.f : 0.f);  // G = I + 2*Sum M^i
            __nv_bfloat16 hi = __float2bfloat16(val);
            float lo = val - __bfloat162float(hi);
            g_Cthi[(j0 + c)*D + row] = hi;                          // [n][k], coalesced in row
            g_Ctlo[(j0 + c)*D + row] = __float2bfloat16(lo);
        }
    }
}

// ---------------- main GEMM via HMMA: out = (Ahi+Alo)Bhi + Ahi*Blo ----------------
// 128x128 tile, 256 threads = 8 warps (4 x 2), warp tile 32(M) x 64(N), K chunks of 64.
// A/B staged in smem directly in m16n8k16 fragment order:
//   A element (m, k):  f=m>>4, s=k>>4, lane=(m&7)*4+((k&7)>>1), reg=((m>>3)&1)+2*((k>>3)&1)
//   B element (k, n): nf=n>>3, s=k>>4, lane=(n&7)*4+((k&7)>>1), reg=(k>>3)&1
__global__ void __launch_bounds__(256) k_mma(const float* __restrict__ q,
                                             const float* __restrict__ kk,
                                             float* __restrict__ out,
                                             int BN, int N) {
    extern __shared__ uint32_t sm[];
    uint32_t* sAhi = sm;
    uint32_t* sAlo = sm + 4096;
    uint32_t* sBhi = sm + 8192;
    uint32_t* sBlo = sm + 12288;

    const int t = threadIdx.x, lane = t & 31, wid = t >> 5;
    const int wr = wid >> 1, wc = wid & 1;
    const int row0 = blockIdx.x * TILE_M;
    const int col0 = blockIdx.y * TILE_N;

    const float* src; int rb;
    if (row0 < BN) { src = q; rb = row0; } else { src = kk; rb = row0 - BN; }
    const int nb = rb % N;   // tile never crosses batch boundary (N multiple of 128)

    float acc[2][8][4];
    #pragma unroll
    for (int f2 = 0; f2 < 2; f2++)
        #pragma unroll
        for (int b2 = 0; b2 < 8; b2++)
            #pragma unroll
            for (int e = 0; e < 4; e++) acc[f2][b2][e] = 0.f;

    const uint32_t* Bhi32 = (const uint32_t*)g_Cthi;
    const uint32_t* Blo32 = (const uint32_t*)g_Ctlo;

    for (int ch = 0; ch < 4; ch++) {
        // ---- stage A chunk with RoPE + hi/lo split (16 u32 per thread) ----
        #pragma unroll 4
        for (int i = 0; i < 16; i++) {
            int idx = i*256 + t;
            int m = idx >> 5, pj = idx & 31;     // local k-pair pj -> k = 2*pj
            int jp = ch*32 + pj;                 // global rotation pair
            float2 v  = *(const float2*)(src + (size_t)(rb + m)*D + 2*jp);
            float2 cs = g_cs[(size_t)(nb + m)*HALF_D + jp];
            float e = v.x*cs.x - v.y*cs.y;
            float o = v.x*cs.y + v.y*cs.x;
            __nv_bfloat16 he = __float2bfloat16(e), ho = __float2bfloat16(o);
            uint32_t hp = ((uint32_t)__bfloat16_as_ushort(ho) << 16) | __bfloat16_as_ushort(he);
            float le = e - __bfloat162float(he), lo = o - __bfloat162float(ho);
            __nv_bfloat16 ge = __float2bfloat16(le), go = __float2bfloat16(lo);
            uint32_t lp = ((uint32_t)__bfloat16_as_ushort(go) << 16) | __bfloat16_as_ushort(ge);
            int addr = ((((m>>4)*4 + (pj>>3))*32 + (m&7)*4 + (pj&3)) << 2)
                     + ((m>>3)&1) + 2*((pj>>2)&1);
            sAhi[addr] = hp;
            sAlo[addr] = lp;
        }
        // ---- stage B chunk from precomputed B^T (16 u32 per thread each) ----
        #pragma unroll 4
        for (int i = 0; i < 16; i++) {
            int idx = i*256 + t;
            int n = idx >> 5, pj = idx & 31;
            int gidx = (col0 + n)*(D/2) + ch*32 + pj;   // u32 index into [n][k] bf16
            uint32_t vh = Bhi32[gidx];
            uint32_t vl = Blo32[gidx];
            int addr = ((((n>>3)*4 + (pj>>3))*32 + (n&7)*4 + (pj&3)) << 1)
                     + ((pj>>2)&1);
            sBhi[addr] = vh;
            sBlo[addr] = vl;
        }
        __syncthreads();

        // ---- compute: 4 k16-steps, 3 passes ----
        #pragma unroll
        for (int s = 0; s < 4; s++) {
            uint4 ah0 = ((const uint4*)sAhi)[((wr*2 + 0)*4 + s)*32 + lane];
            uint4 ah1 = ((const uint4*)sAhi)[((wr*2 + 1)*4 + s)*32 + lane];
            uint4 al0 = ((const uint4*)sAlo)[((wr*2 + 0)*4 + s)*32 + lane];
            uint4 al1 = ((const uint4*)sAlo)[((wr*2 + 1)*4 + s)*32 + lane];
            #pragma unroll
            for (int b2 = 0; b2 < 8; b2++) {
                uint2 bh = ((const uint2*)sBhi)[((wc*8 + b2)*4 + s)*32 + lane];
                uint2 bl = ((const uint2*)sBlo)[((wc*8 + b2)*4 + s)*32 + lane];
                mma16816(acc[0][b2], ah0, bh);
                mma16816(acc[1][b2], ah1, bh);
                mma16816(acc[0][b2], al0, bh);
                mma16816(acc[1][b2], al1, bh);
                mma16816(acc[0][b2], ah0, bl);
                mma16816(acc[1][b2], ah1, bl);
            }
        }
        __syncthreads();
    }

    // ---- epilogue: fragment -> out (float2 stores) ----
    const int g  = lane >> 2, tq = lane & 3;
    #pragma unroll
    for (int f2 = 0; f2 < 2; f2++) {
        int m0 = row0 + (wr*2 + f2)*16 + g;
        #pragma unroll
        for (int b2 = 0; b2 < 8; b2++) {
            int n0 = col0 + (wc*8 + b2)*8 + tq*2;
            *(float2*)&out[(size_t)m0*D + n0]     = make_float2(acc[f2][b2][0], acc[f2][b2][1]);
            *(float2*)&out[(size_t)(m0+8)*D + n0] = make_float2(acc[f2][b2][2], acc[f2][b2][3]);
        }
    }
}

// ---------------- launcher: 3 launches total ----------------
extern "C" void kernel_launch(void* const* d_in, const int* in_sizes, int n_in,
                              void* d_out, int out_size) {
    const float* q     = (const float*)d_in[0];
    const float* k     = (const float*)d_in[1];
    const float* freqs = (const float*)d_in[2];
    const float* sp    = (const float*)d_in[3];
    const int*   pos   = (const int*)  d_in[4];
    const int*   rows  = (const int*)  d_in[5];
    const int*   cols  = (const int*)  d_in[6];
    float* out = (float*)d_out;

    int E    = in_sizes[3];
    int N    = in_sizes[4];
    int BN   = in_sizes[0] / D;   // rows of q (= B*N)
    int ROWS = 2 * BN;

    k_build<<<D, 256>>>(rows, cols, sp, E);

    int tableBlocks = (N*HALF_D + 511)/512;
    k_prep<<<64 + tableBlocks, 512>>>(pos, freqs, N);

    cudaFuncSetAttribute(k_mma, cudaFuncAttributeMaxDynamicSharedMemorySize, SMEM_BYTES);
    dim3 grid(ROWS/TILE_M, D/TILE_N);
    k_mma<<<grid, 256, SMEM_BYTES>>>(q, k, out, BN, N);
}